// round 16
// baseline (speedup 1.0000x reference)
#include <cuda_runtime.h>
#include <stdint.h>
#include <math.h>

// ---------------------------------------------------------------------------
// RandomPhongShader: N=8, H=256, W=256, K=8, NB_SAMPLES=4
// SIGMA=0.1, GAMMA=0.1, ZNEAR=1, ZFAR=100, EPS=1e-10
//
// JAX threefry PRNG, partitionable mode:
//   random_bits(32)[i] = out0 ^ out1 of threefry(key, hi=0, lo=i)
//
// R16 = R10 (measured optimum) + branchless erfinv: both Giles polynomial
// arms evaluated unconditionally (extra FFMAs on the 28%-loaded FMA pipe),
// one SEL picks the result -- removes 36 BSSY/BSYNC pairs per pixel
// (ptxas never emits 0-BSSY predication for C++ if{}; SASS_QUICKREF).
// Selected values come from the identical op sequence -> bit-exact.
// rel_err canary: 1.287565e-08.
// ---------------------------------------------------------------------------

#define NPIX (8 * 256 * 256)          // 524288 pixels
#define STRIDE_H 4194304u             // N*H*W*K     (per-sample stride, noise_h)
#define STRIDE_A 4718592u             // N*H*W*(K+1) (per-sample stride, noise_a)

// Full Threefry-2x32 with x0 = 0 (hi), x1 = ctr (lo); returns out0 ^ out1.
__device__ __forceinline__ uint32_t tf_xor(uint32_t k0, uint32_t k1, uint32_t ctr)
{
    uint32_t k2 = k0 ^ k1 ^ 0x1BD11BDAu;
    uint32_t x0 = k0;          // 0 + k0
    uint32_t x1 = ctr + k1;
#define TFR(r) { x0 += x1; x1 = __funnelshift_l(x1, x1, (r)); x1 ^= x0; }
    TFR(13) TFR(15) TFR(26) TFR(6)
    x0 += k1; x1 += k2 + 1u;
    TFR(17) TFR(29) TFR(16) TFR(24)
    x0 += k2; x1 += k0 + 2u;
    TFR(13) TFR(15) TFR(26) TFR(6)
    x0 += k0; x1 += k1 + 3u;
    TFR(17) TFR(29) TFR(16) TFR(24)
    x0 += k1; x1 += k2 + 4u;
    TFR(13) TFR(15) TFR(26) TFR(6)
    x0 += k2; x1 += k0 + 5u;
#undef TFR
    return x0 ^ x1;
}

// Giles erf_inv (same coefficients as XLA), BRANCHLESS: both arms evaluated,
// SEL at the end. Selected lane's value = identical op sequence as branchy
// version -> bit-exact.
__device__ __forceinline__ float erfinv_fast(float x)
{
    float t = __fmaf_rn(-x, x, 1.0f);          // 1 - x*x
    float w = -__logf(t);                      // MUFU LG2 * ln2; w >= 0

    // near arm (w < 5)
    float w1 = w - 2.5f;
    float p1 = 2.81022636e-08f;
    p1 = __fmaf_rn(p1, w1, 3.43273939e-07f);
    p1 = __fmaf_rn(p1, w1, -3.5233877e-06f);
    p1 = __fmaf_rn(p1, w1, -4.39150654e-06f);
    p1 = __fmaf_rn(p1, w1, 0.00021858087f);
    p1 = __fmaf_rn(p1, w1, -0.00125372503f);
    p1 = __fmaf_rn(p1, w1, -0.00417768164f);
    p1 = __fmaf_rn(p1, w1, 0.246640727f);
    p1 = __fmaf_rn(p1, w1, 1.50140941f);

    // far arm (w >= 5)
    float w2 = sqrtf(w) - 3.0f;
    float p2 = -0.000200214257f;
    p2 = __fmaf_rn(p2, w2, 0.000100950558f);
    p2 = __fmaf_rn(p2, w2, 0.00134934322f);
    p2 = __fmaf_rn(p2, w2, -0.00367342844f);
    p2 = __fmaf_rn(p2, w2, 0.00573950773f);
    p2 = __fmaf_rn(p2, w2, -0.0076224613f);
    p2 = __fmaf_rn(p2, w2, 0.00943887047f);
    p2 = __fmaf_rn(p2, w2, 1.00167406f);
    p2 = __fmaf_rn(p2, w2, 2.83297682f);

    float p = (w < 5.0f) ? p1 : p2;
    return p * x;
}

// m = bits>>9 -> N(0,1); exact same fp sequence as the reference mapping.
__device__ __forceinline__ float m_to_normal(uint32_t m)
{
    const float LO    = __uint_as_float(0xBF7FFFFFu);  // nextafter(-1, 0)
    const float SQRT2 = __uint_as_float(0x3FB504F3u);  // float32(sqrt(2))
    float u = __fmaf_rn((float)m, 0x1.0p-22f, LO);     // exact prod, 1 rounding
    return SQRT2 * erfinv_fast(u);
}

// Rare exact heaviside fallback; out of line to keep the hot path small.
__device__ __noinline__ int heaviside_exact(float x, uint32_t m)
{
    return (__fadd_rn(x, __fmul_rn(0.1f, m_to_normal(m))) >= 0.0f) ? 1 : 0;
}

// Abramowitz-Stegun 7.1.26 erf, |abs err| <= ~1.5e-7 (plus expf/div ~1e-7).
__device__ __forceinline__ float erf_approx(float z)
{
    float az = fminf(fabsf(z), 4.0f);      // erf(4) = 1 - 1.5e-8, saturate
    float t  = __fdividef(1.0f, __fmaf_rn(0.3275911f, az, 1.0f));
    float y  = 1.061405429f;
    y = __fmaf_rn(y, t, -1.453152027f);
    y = __fmaf_rn(y, t,  1.421413741f);
    y = __fmaf_rn(y, t, -0.284496736f);
    y = __fmaf_rn(y, t,  0.254829592f);
    y = y * t;
    float e = __expf(-az * az);
    float r = __fmaf_rn(-y, e, 1.0f);
    return (z < 0.0f) ? -r : r;
}

__global__ void __launch_bounds__(256, 8)
rps_kernel(const float* __restrict__ colors,   // (N,H,W,K,3)
           const float* __restrict__ dists,    // (N,H,W,K)
           const float* __restrict__ zbuf,     // (N,H,W,K)
           const int*   __restrict__ p2f,      // (N,H,W,K)
           const float* __restrict__ bg,       // (3,)
           float*       __restrict__ out,      // (N,H,W,4)
           uint32_t kh0, uint32_t kh1, uint32_t ka0, uint32_t ka1,
           float l0, float l1, float l2, float l3, float l4)
{
    __shared__ float2 zl_s[8 * 256];   // (zinv, logp) per face per thread
    __shared__ float  lut_s[5];

    unsigned tid = threadIdx.x;
    unsigned pix = blockIdx.x * 256u + tid;   // grid is exactly NPIX/256

    if (tid == 0) {
        lut_s[0] = l0; lut_s[1] = l1; lut_s[2] = l2; lut_s[3] = l3; lut_s[4] = l4;
    }
    __syncthreads();

    const float* dp = dists + (size_t)pix * 8;
    const float* zp = zbuf  + (size_t)pix * 8;
    const int*   fp = p2f   + (size_t)pix * 8;

    // ---- phase 1: heaviside via integer threshold; alpha; (zinv,logp) ------
    float alpha = 1.0f;
    float zmax  = -1e30f;
    uint32_t bh = pix * 8u;

#pragma unroll 1
    for (int k = 0; k < 8; ++k) {
        float d = __ldg(dp + k);
        float z = __ldg(zp + k);
        int   f = __ldg(fp + k);
        bool msk = (f >= 0);
        float mask = msk ? 1.0f : 0.0f;
        uint32_t b = bh + (uint32_t)k;
        float x = -d;

        // threshold on m = bits>>9: decision is (m >= m*), |m* - mth| << 64
        float uth = erf_approx(d * 7.0710678f);                 // erf(10d/sqrt2)
        // (uth - LO)*2^22 ; -LO*2^22 = (1-2^-24)*2^22 = 4194303.75 exactly
        int mth = __float2int_rn(__fmaf_rn(uth, 4194304.0f, 4194303.75f));
        int mhi = mth + 64;
        int mlo = mth - 64;

        int cnt = 0;
#pragma unroll
        for (int s = 0; s < 4; ++s) {
            uint32_t bits = tf_xor(kh0, kh1, b + (uint32_t)s * STRIDE_H);
            int m = (int)(bits >> 9);
            if (m >= mhi) {
                cnt++;
            } else if (m > mlo) {   // rare exact fallback (~3e-5 per sample)
                cnt += heaviside_exact(x, (uint32_t)m);
            }
        }

        int idx = msk ? cnt : 0;
        float prob = __fmul_rn((float)cnt * 0.25f, mask);   // exact
        alpha = __fmul_rn(alpha, 1.0f - prob);              // exact product
        float zinvk = __fmul_rn(__fdiv_rn(__fsub_rn(100.0f, z), 99.0f), mask);
        zmax = fmaxf(zmax, zinvk);
        float2 zl; zl.x = zinvk; zl.y = lut_s[idx];
        zl_s[k * 256 + tid] = zl;
    }
    zmax = fmaxf(zmax, 1e-10f);

    // ---- phase 2: random argmax, faces j=0..7, 4 samples, first-max-wins ---
    float b0 = -1e30f, b1 = -1e30f, b2 = -1e30f, b3 = -1e30f;
    int   i0 = 0, i1 = 0, i2 = 0, i3 = 0;
    uint32_t ba = pix * 9u;

#pragma unroll 2
    for (int j = 0; j < 8; ++j) {
        float2 zl = zl_s[j * 256 + tid];
        float zmj = __fadd_rn(zl.y, __fdiv_rn(__fsub_rn(zl.x, zmax), 0.1f));

        uint32_t c = ba + (uint32_t)j;
        float s0 = __fadd_rn(zmj, __fmul_rn(0.1f, m_to_normal(tf_xor(ka0, ka1, c) >> 9)));
        float s1 = __fadd_rn(zmj, __fmul_rn(0.1f, m_to_normal(tf_xor(ka0, ka1, c + STRIDE_A) >> 9)));
        float s2 = __fadd_rn(zmj, __fmul_rn(0.1f, m_to_normal(tf_xor(ka0, ka1, c + 2u * STRIDE_A) >> 9)));
        float s3 = __fadd_rn(zmj, __fmul_rn(0.1f, m_to_normal(tf_xor(ka0, ka1, c + 3u * STRIDE_A) >> 9)));
        if (s0 > b0) { b0 = s0; i0 = j; }
        if (s1 > b1) { b1 = s1; i1 = j; }
        if (s2 > b2) { b2 = s2; i2 = j; }
        if (s3 > b3) { b3 = s3; i3 = j; }
    }
    // Background (j=8): max |0.1*noise| = 0.543 < 0.6; if zm8 can't reach the
    // weakest running best it can never win any sample -> skip (~never taken).
    {
        float zm8 = __fdiv_rn(__fsub_rn(1e-10f, zmax), 0.1f);
        float bmin = fminf(fminf(b0, b1), fminf(b2, b3));
        if (zm8 > bmin - 0.6f) {
            uint32_t c = ba + 8u;
            float s0 = __fadd_rn(zm8, __fmul_rn(0.1f, m_to_normal(tf_xor(ka0, ka1, c) >> 9)));
            float s1 = __fadd_rn(zm8, __fmul_rn(0.1f, m_to_normal(tf_xor(ka0, ka1, c + STRIDE_A) >> 9)));
            float s2 = __fadd_rn(zm8, __fmul_rn(0.1f, m_to_normal(tf_xor(ka0, ka1, c + 2u * STRIDE_A) >> 9)));
            float s3 = __fadd_rn(zm8, __fmul_rn(0.1f, m_to_normal(tf_xor(ka0, ka1, c + 3u * STRIDE_A) >> 9)));
            if (s0 > b0) { i0 = 8; }
            if (s1 > b1) { i1 = 8; }
            if (s2 > b2) { i2 = 8; }
            if (s3 > b3) { i3 = 8; }
        }
    }

    // ---- phase 3: weighted colors (reference summation order k=0..7) ------
    const float* cp = colors + (size_t)pix * 24;
    float r = 0.f, g = 0.f, bl = 0.f;
#pragma unroll 1
    for (int k = 0; k < 8; ++k) {
        int cnt = (i0 == k) + (i1 == k) + (i2 == k) + (i3 == k);
        float wk = __fmul_rn((float)cnt, 0.25f);
        r  = __fadd_rn(r,  __fmul_rn(wk, __ldg(cp + 3 * k + 0)));
        g  = __fadd_rn(g,  __fmul_rn(wk, __ldg(cp + 3 * k + 1)));
        bl = __fadd_rn(bl, __fmul_rn(wk, __ldg(cp + 3 * k + 2)));
    }
    int cntb = (i0 == 8) + (i1 == 8) + (i2 == 8) + (i3 == 8);
    float wb = __fmul_rn((float)cntb, 0.25f);

    float4 o;
    o.x = __fadd_rn(r,  __fmul_rn(wb, bg[0]));
    o.y = __fadd_rn(g,  __fmul_rn(wb, bg[1]));
    o.z = __fadd_rn(bl, __fmul_rn(wb, bg[2]));
    o.w = 1.0f - alpha;
    *(float4*)(out + (size_t)pix * 4) = o;
}

// ---------------------------------------------------------------------------
// Host-side threefry for key derivation (full 2-word output).
// ---------------------------------------------------------------------------
static void threefry_host(uint32_t k0, uint32_t k1, uint32_t x0, uint32_t x1,
                          uint32_t* o0, uint32_t* o1)
{
    uint32_t k2 = k0 ^ k1 ^ 0x1BD11BDAu;
    x0 += k0; x1 += k1;
#define R(r) { x0 += x1; x1 = (x1 << (r)) | (x1 >> (32 - (r))); x1 ^= x0; }
    R(13) R(15) R(26) R(6)
    x0 += k1; x1 += k2 + 1u;
    R(17) R(29) R(16) R(24)
    x0 += k2; x1 += k0 + 2u;
    R(13) R(15) R(26) R(6)
    x0 += k0; x1 += k1 + 3u;
    R(17) R(29) R(16) R(24)
    x0 += k1; x1 += k2 + 4u;
    R(13) R(15) R(26) R(6)
    x0 += k2; x1 += k0 + 5u;
#undef R
    *o0 = x0; *o1 = x1;
}

extern "C" void kernel_launch(void* const* d_in, const int* in_sizes, int n_in,
                              void* d_out, int out_size)
{
    const float* colors = (const float*)d_in[0];
    const float* dists  = (const float*)d_in[1];
    const float* zbuf   = (const float*)d_in[2];
    const int*   p2f    = (const int*)  d_in[3];
    const float* bg     = (const float*)d_in[4];
    float*       out    = (float*)d_out;

    // jax.random.key(1) -> raw key (0, 1); partitionable split.
    uint32_t kh0, kh1, ka0, ka1;
    threefry_host(0u, 1u, 0u, 0u, &kh0, &kh1);   // kh = keys[0]
    threefry_host(0u, 1u, 0u, 1u, &ka0, &ka1);   // ka = keys[1]

    // log(EPS + prob) LUT, prob in {0, 0.25, 0.5, 0.75, 1.0}.
    float l0 = (float)log((double)1e-10f);
    float l1 = (float)log((double)(1e-10f + 0.25f));
    float l2 = (float)log((double)(1e-10f + 0.5f));
    float l3 = (float)log((double)(1e-10f + 0.75f));
    float l4 = (float)log((double)(1e-10f + 1.0f));

    dim3 grid(NPIX / 256);
    rps_kernel<<<grid, 256>>>(colors, dists, zbuf, p2f, bg, out,
                              kh0, kh1, ka0, ka1, l0, l1, l2, l3, l4);
}

// round 17
// speedup vs baseline: 1.0572x; 1.0572x over previous
#include <cuda_runtime.h>
#include <stdint.h>
#include <math.h>

// ---------------------------------------------------------------------------
// RandomPhongShader: N=8, H=256, W=256, K=8, NB_SAMPLES=4
// SIGMA=0.1, GAMMA=0.1, ZNEAR=1, ZFAR=100, EPS=1e-10
//
// JAX threefry PRNG, partitionable mode:
//   random_bits(32)[i] = out0 ^ out1 of threefry(key, hi=0, lo=i)
//
// FINAL == R10, the measured optimum (128.0-128.2us kernel across runs).
//  - Heaviside via integer threshold on m = bits>>9 (decision-identical;
//    rare __noinline__ exact fallback, ~3e-5/sample).
//  - (zinv, logp) staged as float2 in smem; logp from a 5-word LUT.
//  - Per-lane background prune (margin 0.6 > max|0.1*noise| = 0.543).
//  - Outer loops not unrolled (hot code fits 32KB L1.5 I$).
//  - __launch_bounds__(256,8): 32 regs, 8 CTAs/SM, occ ~76%.
// Measured WORSE and reverted: IMAD pipe-forcing (R6/R11), warp-compacted
// heaviside (R12/R13), 2 pixels/thread (R14), branchless erfinv (R16 --
// the w<5 branch is warp-uniform ~90% of the time; predication doubled the
// polynomial work for nothing).
// rel_err canary: 1.287565e-08 (bit-stable since R5).
// ---------------------------------------------------------------------------

#define NPIX (8 * 256 * 256)          // 524288 pixels
#define STRIDE_H 4194304u             // N*H*W*K     (per-sample stride, noise_h)
#define STRIDE_A 4718592u             // N*H*W*(K+1) (per-sample stride, noise_a)

// Full Threefry-2x32 with x0 = 0 (hi), x1 = ctr (lo); returns out0 ^ out1.
__device__ __forceinline__ uint32_t tf_xor(uint32_t k0, uint32_t k1, uint32_t ctr)
{
    uint32_t k2 = k0 ^ k1 ^ 0x1BD11BDAu;
    uint32_t x0 = k0;          // 0 + k0
    uint32_t x1 = ctr + k1;
#define TFR(r) { x0 += x1; x1 = __funnelshift_l(x1, x1, (r)); x1 ^= x0; }
    TFR(13) TFR(15) TFR(26) TFR(6)
    x0 += k1; x1 += k2 + 1u;
    TFR(17) TFR(29) TFR(16) TFR(24)
    x0 += k2; x1 += k0 + 2u;
    TFR(13) TFR(15) TFR(26) TFR(6)
    x0 += k0; x1 += k1 + 3u;
    TFR(17) TFR(29) TFR(16) TFR(24)
    x0 += k1; x1 += k2 + 4u;
    TFR(13) TFR(15) TFR(26) TFR(6)
    x0 += k2; x1 += k0 + 5u;
#undef TFR
    return x0 ^ x1;
}

// Giles erf_inv (same coefficients as XLA), FMA form + MUFU log.
__device__ __forceinline__ float erfinv_fast(float x)
{
    float t = __fmaf_rn(-x, x, 1.0f);          // 1 - x*x
    float w = -__logf(t);                      // MUFU LG2 * ln2
    float p;
    if (w < 5.0f) {
        w = w - 2.5f;
        p = 2.81022636e-08f;
        p = __fmaf_rn(p, w, 3.43273939e-07f);
        p = __fmaf_rn(p, w, -3.5233877e-06f);
        p = __fmaf_rn(p, w, -4.39150654e-06f);
        p = __fmaf_rn(p, w, 0.00021858087f);
        p = __fmaf_rn(p, w, -0.00125372503f);
        p = __fmaf_rn(p, w, -0.00417768164f);
        p = __fmaf_rn(p, w, 0.246640727f);
        p = __fmaf_rn(p, w, 1.50140941f);
    } else {
        w = sqrtf(w) - 3.0f;
        p = -0.000200214257f;
        p = __fmaf_rn(p, w, 0.000100950558f);
        p = __fmaf_rn(p, w, 0.00134934322f);
        p = __fmaf_rn(p, w, -0.00367342844f);
        p = __fmaf_rn(p, w, 0.00573950773f);
        p = __fmaf_rn(p, w, -0.0076224613f);
        p = __fmaf_rn(p, w, 0.00943887047f);
        p = __fmaf_rn(p, w, 1.00167406f);
        p = __fmaf_rn(p, w, 2.83297682f);
    }
    return p * x;
}

// m = bits>>9 -> N(0,1); exact same fp sequence as the reference mapping.
__device__ __forceinline__ float m_to_normal(uint32_t m)
{
    const float LO    = __uint_as_float(0xBF7FFFFFu);  // nextafter(-1, 0)
    const float SQRT2 = __uint_as_float(0x3FB504F3u);  // float32(sqrt(2))
    float u = __fmaf_rn((float)m, 0x1.0p-22f, LO);     // exact prod, 1 rounding
    return SQRT2 * erfinv_fast(u);
}

// Rare exact heaviside fallback; out of line to keep the hot path small.
__device__ __noinline__ int heaviside_exact(float x, uint32_t m)
{
    return (__fadd_rn(x, __fmul_rn(0.1f, m_to_normal(m))) >= 0.0f) ? 1 : 0;
}

// Abramowitz-Stegun 7.1.26 erf, |abs err| <= ~1.5e-7 (plus expf/div ~1e-7).
__device__ __forceinline__ float erf_approx(float z)
{
    float az = fminf(fabsf(z), 4.0f);      // erf(4) = 1 - 1.5e-8, saturate
    float t  = __fdividef(1.0f, __fmaf_rn(0.3275911f, az, 1.0f));
    float y  = 1.061405429f;
    y = __fmaf_rn(y, t, -1.453152027f);
    y = __fmaf_rn(y, t,  1.421413741f);
    y = __fmaf_rn(y, t, -0.284496736f);
    y = __fmaf_rn(y, t,  0.254829592f);
    y = y * t;
    float e = __expf(-az * az);
    float r = __fmaf_rn(-y, e, 1.0f);
    return (z < 0.0f) ? -r : r;
}

__global__ void __launch_bounds__(256, 8)
rps_kernel(const float* __restrict__ colors,   // (N,H,W,K,3)
           const float* __restrict__ dists,    // (N,H,W,K)
           const float* __restrict__ zbuf,     // (N,H,W,K)
           const int*   __restrict__ p2f,      // (N,H,W,K)
           const float* __restrict__ bg,       // (3,)
           float*       __restrict__ out,      // (N,H,W,4)
           uint32_t kh0, uint32_t kh1, uint32_t ka0, uint32_t ka1,
           float l0, float l1, float l2, float l3, float l4)
{
    __shared__ float2 zl_s[8 * 256];   // (zinv, logp) per face per thread
    __shared__ float  lut_s[5];

    unsigned tid = threadIdx.x;
    unsigned pix = blockIdx.x * 256u + tid;   // grid is exactly NPIX/256

    if (tid == 0) {
        lut_s[0] = l0; lut_s[1] = l1; lut_s[2] = l2; lut_s[3] = l3; lut_s[4] = l4;
    }
    __syncthreads();

    const float* dp = dists + (size_t)pix * 8;
    const float* zp = zbuf  + (size_t)pix * 8;
    const int*   fp = p2f   + (size_t)pix * 8;

    // ---- phase 1: heaviside via integer threshold; alpha; (zinv,logp) ------
    float alpha = 1.0f;
    float zmax  = -1e30f;
    uint32_t bh = pix * 8u;

#pragma unroll 1
    for (int k = 0; k < 8; ++k) {
        float d = __ldg(dp + k);
        float z = __ldg(zp + k);
        int   f = __ldg(fp + k);
        bool msk = (f >= 0);
        float mask = msk ? 1.0f : 0.0f;
        uint32_t b = bh + (uint32_t)k;
        float x = -d;

        // threshold on m = bits>>9: decision is (m >= m*), |m* - mth| << 64
        float uth = erf_approx(d * 7.0710678f);                 // erf(10d/sqrt2)
        // (uth - LO)*2^22 ; -LO*2^22 = (1-2^-24)*2^22 = 4194303.75 exactly
        int mth = __float2int_rn(__fmaf_rn(uth, 4194304.0f, 4194303.75f));
        int mhi = mth + 64;
        int mlo = mth - 64;

        int cnt = 0;
#pragma unroll
        for (int s = 0; s < 4; ++s) {
            uint32_t bits = tf_xor(kh0, kh1, b + (uint32_t)s * STRIDE_H);
            int m = (int)(bits >> 9);
            if (m >= mhi) {
                cnt++;
            } else if (m > mlo) {   // rare exact fallback (~3e-5 per sample)
                cnt += heaviside_exact(x, (uint32_t)m);
            }
        }

        int idx = msk ? cnt : 0;
        float prob = __fmul_rn((float)cnt * 0.25f, mask);   // exact
        alpha = __fmul_rn(alpha, 1.0f - prob);              // exact product
        float zinvk = __fmul_rn(__fdiv_rn(__fsub_rn(100.0f, z), 99.0f), mask);
        zmax = fmaxf(zmax, zinvk);
        float2 zl; zl.x = zinvk; zl.y = lut_s[idx];
        zl_s[k * 256 + tid] = zl;
    }
    zmax = fmaxf(zmax, 1e-10f);

    // ---- phase 2: random argmax, faces j=0..7, 4 samples, first-max-wins ---
    float b0 = -1e30f, b1 = -1e30f, b2 = -1e30f, b3 = -1e30f;
    int   i0 = 0, i1 = 0, i2 = 0, i3 = 0;
    uint32_t ba = pix * 9u;

#pragma unroll 2
    for (int j = 0; j < 8; ++j) {
        float2 zl = zl_s[j * 256 + tid];
        float zmj = __fadd_rn(zl.y, __fdiv_rn(__fsub_rn(zl.x, zmax), 0.1f));

        uint32_t c = ba + (uint32_t)j;
        float s0 = __fadd_rn(zmj, __fmul_rn(0.1f, m_to_normal(tf_xor(ka0, ka1, c) >> 9)));
        float s1 = __fadd_rn(zmj, __fmul_rn(0.1f, m_to_normal(tf_xor(ka0, ka1, c + STRIDE_A) >> 9)));
        float s2 = __fadd_rn(zmj, __fmul_rn(0.1f, m_to_normal(tf_xor(ka0, ka1, c + 2u * STRIDE_A) >> 9)));
        float s3 = __fadd_rn(zmj, __fmul_rn(0.1f, m_to_normal(tf_xor(ka0, ka1, c + 3u * STRIDE_A) >> 9)));
        if (s0 > b0) { b0 = s0; i0 = j; }
        if (s1 > b1) { b1 = s1; i1 = j; }
        if (s2 > b2) { b2 = s2; i2 = j; }
        if (s3 > b3) { b3 = s3; i3 = j; }
    }
    // Background (j=8): max |0.1*noise| = 0.543 < 0.6; if zm8 can't reach the
    // weakest running best it can never win any sample -> skip (~never taken).
    {
        float zm8 = __fdiv_rn(__fsub_rn(1e-10f, zmax), 0.1f);
        float bmin = fminf(fminf(b0, b1), fminf(b2, b3));
        if (zm8 > bmin - 0.6f) {
            uint32_t c = ba + 8u;
            float s0 = __fadd_rn(zm8, __fmul_rn(0.1f, m_to_normal(tf_xor(ka0, ka1, c) >> 9)));
            float s1 = __fadd_rn(zm8, __fmul_rn(0.1f, m_to_normal(tf_xor(ka0, ka1, c + STRIDE_A) >> 9)));
            float s2 = __fadd_rn(zm8, __fmul_rn(0.1f, m_to_normal(tf_xor(ka0, ka1, c + 2u * STRIDE_A) >> 9)));
            float s3 = __fadd_rn(zm8, __fmul_rn(0.1f, m_to_normal(tf_xor(ka0, ka1, c + 3u * STRIDE_A) >> 9)));
            if (s0 > b0) { i0 = 8; }
            if (s1 > b1) { i1 = 8; }
            if (s2 > b2) { i2 = 8; }
            if (s3 > b3) { i3 = 8; }
        }
    }

    // ---- phase 3: weighted colors (reference summation order k=0..7) ------
    const float* cp = colors + (size_t)pix * 24;
    float r = 0.f, g = 0.f, bl = 0.f;
#pragma unroll 1
    for (int k = 0; k < 8; ++k) {
        int cnt = (i0 == k) + (i1 == k) + (i2 == k) + (i3 == k);
        float wk = __fmul_rn((float)cnt, 0.25f);
        r  = __fadd_rn(r,  __fmul_rn(wk, __ldg(cp + 3 * k + 0)));
        g  = __fadd_rn(g,  __fmul_rn(wk, __ldg(cp + 3 * k + 1)));
        bl = __fadd_rn(bl, __fmul_rn(wk, __ldg(cp + 3 * k + 2)));
    }
    int cntb = (i0 == 8) + (i1 == 8) + (i2 == 8) + (i3 == 8);
    float wb = __fmul_rn((float)cntb, 0.25f);

    float4 o;
    o.x = __fadd_rn(r,  __fmul_rn(wb, bg[0]));
    o.y = __fadd_rn(g,  __fmul_rn(wb, bg[1]));
    o.z = __fadd_rn(bl, __fmul_rn(wb, bg[2]));
    o.w = 1.0f - alpha;
    *(float4*)(out + (size_t)pix * 4) = o;
}

// ---------------------------------------------------------------------------
// Host-side threefry for key derivation (full 2-word output).
// ---------------------------------------------------------------------------
static void threefry_host(uint32_t k0, uint32_t k1, uint32_t x0, uint32_t x1,
                          uint32_t* o0, uint32_t* o1)
{
    uint32_t k2 = k0 ^ k1 ^ 0x1BD11BDAu;
    x0 += k0; x1 += k1;
#define R(r) { x0 += x1; x1 = (x1 << (r)) | (x1 >> (32 - (r))); x1 ^= x0; }
    R(13) R(15) R(26) R(6)
    x0 += k1; x1 += k2 + 1u;
    R(17) R(29) R(16) R(24)
    x0 += k2; x1 += k0 + 2u;
    R(13) R(15) R(26) R(6)
    x0 += k0; x1 += k1 + 3u;
    R(17) R(29) R(16) R(24)
    x0 += k1; x1 += k2 + 4u;
    R(13) R(15) R(26) R(6)
    x0 += k2; x1 += k0 + 5u;
#undef R
    *o0 = x0; *o1 = x1;
}

extern "C" void kernel_launch(void* const* d_in, const int* in_sizes, int n_in,
                              void* d_out, int out_size)
{
    const float* colors = (const float*)d_in[0];
    const float* dists  = (const float*)d_in[1];
    const float* zbuf   = (const float*)d_in[2];
    const int*   p2f    = (const int*)  d_in[3];
    const float* bg     = (const float*)d_in[4];
    float*       out    = (float*)d_out;

    // jax.random.key(1) -> raw key (0, 1); partitionable split.
    uint32_t kh0, kh1, ka0, ka1;
    threefry_host(0u, 1u, 0u, 0u, &kh0, &kh1);   // kh = keys[0]
    threefry_host(0u, 1u, 0u, 1u, &ka0, &ka1);   // ka = keys[1]

    // log(EPS + prob) LUT, prob in {0, 0.25, 0.5, 0.75, 1.0}.
    float l0 = (float)log((double)1e-10f);
    float l1 = (float)log((double)(1e-10f + 0.25f));
    float l2 = (float)log((double)(1e-10f + 0.5f));
    float l3 = (float)log((double)(1e-10f + 0.75f));
    float l4 = (float)log((double)(1e-10f + 1.0f));

    dim3 grid(NPIX / 256);
    rps_kernel<<<grid, 256>>>(colors, dists, zbuf, p2f, bg, out,
                              kh0, kh1, ka0, ka1, l0, l1, l2, l3, l4);
}